// round 2
// baseline (speedup 1.0000x reference)
#include <cuda_runtime.h>
#include <cuda_bf16.h>
#include <cstdint>

// ---------------- problem constants ----------------
#define N_USER 200000
#define N_ITEM 100000
#define N_NODE (N_USER + N_ITEM)   // 300000
#define D 64
#define NNZ 2000000
#define N_LAYER 3
#define BATCH 8192

// D floats = 16 float4 per node row
#define D4 (D / 4)

// ---------------- scratch (device globals; no allocation allowed) ----------------
// 4 layer buffers: x0 = input embeddings, x1..x3 = SpMM outputs per layer.
// Each is N_NODE * D floats = 76.8 MB. Layer sum is folded into the final
// dot kernel (only 16384 gathered rows need the sum), saving 3 full
// read-modify-write accumulation passes.
__device__ float g_x0[(size_t)N_NODE * D];
__device__ float g_x1[(size_t)N_NODE * D];
__device__ float g_x2[(size_t)N_NODE * D];
__device__ float g_x3[(size_t)N_NODE * D];

// ---------------- init: fill x0 from emb_u/emb_i, zero x1..x3 ----------------
__global__ void init_kernel(const float4* __restrict__ emb_u,
                            const float4* __restrict__ emb_i) {
    const size_t total4 = (size_t)N_NODE * D4;          // float4 elements
    const size_t user4  = (size_t)N_USER * D4;
    float4* __restrict__ x0 = reinterpret_cast<float4*>(g_x0);
    float4* __restrict__ x1 = reinterpret_cast<float4*>(g_x1);
    float4* __restrict__ x2 = reinterpret_cast<float4*>(g_x2);
    float4* __restrict__ x3 = reinterpret_cast<float4*>(g_x3);
    const float4 z = make_float4(0.f, 0.f, 0.f, 0.f);
    for (size_t i = (size_t)blockIdx.x * blockDim.x + threadIdx.x;
         i < total4;
         i += (size_t)gridDim.x * blockDim.x) {
        float4 v = (i < user4) ? emb_u[i] : emb_i[i - user4];
        x0[i] = v;
        x1[i] = z;
        x2[i] = z;
        x3[i] = z;
    }
}

// ---------------- vectorized global reduction add ----------------
// One 16B reduction instead of 4 scalar atomicAdds: 4x fewer L2 atomic ops.
__device__ __forceinline__ void red_add_v4(float4* addr, float4 v) {
    asm volatile("red.relaxed.gpu.global.add.v4.f32 [%0], {%1, %2, %3, %4};"
                 :: "l"(addr), "f"(v.x), "f"(v.y), "f"(v.z), "f"(v.w)
                 : "memory");
}

// ---------------- COO SpMM: y[row] += val * x[col], 16 threads per edge ----------------
__global__ void spmm_kernel(const int* __restrict__ rows,
                            const int* __restrict__ cols,
                            const float* __restrict__ vals,
                            const float4* __restrict__ x,
                            float4* __restrict__ y) {
    const long long t = (long long)blockIdx.x * blockDim.x + threadIdx.x;
    const long long e = t >> 4;          // edge index
    const int sub = (int)(t & 15);       // which float4 within the 64-float row
    if (e >= NNZ) return;
    const int r = __ldg(rows + e);       // 16-lane broadcast, L1 hit
    const int c = __ldg(cols + e);
    const float v = __ldg(vals + e);
    float4 xv = x[(size_t)c * D4 + sub];
    xv.x *= v; xv.y *= v; xv.z *= v; xv.w *= v;
    red_add_v4(&y[(size_t)r * D4 + sub], xv);
}

// ---------------- final gather + layer-sum + dot ----------------
// out[b] = (1/16) * sum_d ( sum_l xl[u][d] ) * ( sum_l xl[i][d] )
__global__ void dot_kernel(const int* __restrict__ idx_u,
                           const int* __restrict__ idx_i,
                           float* __restrict__ out) {
    const int warp_id = (blockIdx.x * blockDim.x + threadIdx.x) >> 5;
    const int lane = threadIdx.x & 31;
    if (warp_id >= BATCH) return;

    const size_t u_base = (size_t)idx_u[warp_id] * D;
    const size_t i_base = ((size_t)N_USER + idx_i[warp_id]) * D;

    float partial = 0.f;
    #pragma unroll
    for (int k = 0; k < 2; ++k) {
        const int d = lane + k * 32;
        float u = g_x0[u_base + d] + g_x1[u_base + d]
                + g_x2[u_base + d] + g_x3[u_base + d];
        float it = g_x0[i_base + d] + g_x1[i_base + d]
                 + g_x2[i_base + d] + g_x3[i_base + d];
        partial += u * it;
    }
    // warp reduce
    #pragma unroll
    for (int off = 16; off > 0; off >>= 1)
        partial += __shfl_down_sync(0xFFFFFFFFu, partial, off);

    if (lane == 0)
        out[warp_id] = partial * (1.0f / ((N_LAYER + 1) * (N_LAYER + 1)));
}

// ---------------- launcher ----------------
extern "C" void kernel_launch(void* const* d_in, const int* in_sizes, int n_in,
                              void* d_out, int out_size) {
    const float* emb_u    = (const float*)d_in[0];
    const float* emb_i    = (const float*)d_in[1];
    const int*   adj_rows = (const int*)d_in[2];
    const int*   adj_cols = (const int*)d_in[3];
    const float* adj_vals = (const float*)d_in[4];
    const int*   idx_u    = (const int*)d_in[5];
    const int*   idx_i    = (const int*)d_in[6];
    float* out = (float*)d_out;

    float* x0; float* x1; float* x2; float* x3;
    cudaGetSymbolAddress((void**)&x0, g_x0);
    cudaGetSymbolAddress((void**)&x1, g_x1);
    cudaGetSymbolAddress((void**)&x2, g_x2);
    cudaGetSymbolAddress((void**)&x3, g_x3);

    // init: grid-stride over N_NODE * D4 float4 elements
    {
        int threads = 256;
        int blocks = 148 * 16;  // ~one full wave at high occupancy
        init_kernel<<<blocks, threads>>>((const float4*)emb_u, (const float4*)emb_i);
    }

    // 3 SpMM layers: x0 -> x1 -> x2 -> x3
    {
        const long long total_threads = (long long)NNZ * 16;
        int threads = 256;
        int blocks = (int)((total_threads + threads - 1) / threads);
        spmm_kernel<<<blocks, threads>>>(adj_rows, adj_cols, adj_vals,
                                         (const float4*)x0, (float4*)x1);
        spmm_kernel<<<blocks, threads>>>(adj_rows, adj_cols, adj_vals,
                                         (const float4*)x1, (float4*)x2);
        spmm_kernel<<<blocks, threads>>>(adj_rows, adj_cols, adj_vals,
                                         (const float4*)x2, (float4*)x3);
    }

    // final gather + dot: one warp per pair
    {
        int threads = 256;                       // 8 warps per block
        int blocks = (BATCH * 32 + threads - 1) / threads;
        dot_kernel<<<blocks, threads>>>(idx_u, idx_i, out);
    }
}

// round 5
// speedup vs baseline: 1.5389x; 1.5389x over previous
#include <cuda_runtime.h>
#include <cuda_bf16.h>
#include <cstdint>

// ---------------- problem constants ----------------
#define N_USER 200000
#define N_ITEM 100000
#define N_NODE 300000
#define D 64
#define NNZ 2000000
#define BATCH 8192

#define D2 (D / 2)   // float2 per row = 32

// ---------------- scan config ----------------
#define SCAN_T 256
#define SCAN_C 8
#define SCAN_BLK (SCAN_T * SCAN_C)                      // 2048
#define SCAN_NB ((N_NODE + SCAN_BLK - 1) / SCAN_BLK)    // 147

// ---------------- scratch (device globals) ----------------
__device__ float g_x1[(size_t)N_NODE * D];
__device__ float g_x2[(size_t)N_NODE * D];
__device__ float g_x3[(size_t)N_NODE * D];
__device__ int   g_cnt[N_NODE];
__device__ int   g_off[N_NODE + 1];
__device__ int   g_pos[N_NODE];
__device__ int   g_bsum[SCAN_NB];
__device__ int2  g_cv[NNZ];          // packed (col, bitcast(val)) sorted by row

// ---------------- 0: zero counts ----------------
__global__ void zero_cnt_kernel() {
    int i = blockIdx.x * blockDim.x + threadIdx.x;
    if (i < N_NODE) g_cnt[i] = 0;
}

// ---------------- 1: histogram of row degrees ----------------
__global__ void hist_kernel(const int* __restrict__ rows) {
    int e = blockIdx.x * blockDim.x + threadIdx.x;
    if (e < NNZ) atomicAdd(&g_cnt[rows[e]], 1);
}

// ---------------- 2a: per-block sums ----------------
__global__ void scan1_kernel() {
    __shared__ int sh[SCAN_T];
    const int tid = threadIdx.x;
    const int base = blockIdx.x * SCAN_BLK + tid * SCAN_C;
    int s = 0;
    #pragma unroll
    for (int k = 0; k < SCAN_C; ++k) {
        int i = base + k;
        s += (i < N_NODE) ? g_cnt[i] : 0;
    }
    sh[tid] = s;
    __syncthreads();
    for (int o = SCAN_T / 2; o > 0; o >>= 1) {
        if (tid < o) sh[tid] += sh[tid + o];
        __syncthreads();
    }
    if (tid == 0) g_bsum[blockIdx.x] = sh[0];
}

// ---------------- 2b: serial exclusive scan of block sums (147 elems) ----------------
__global__ void scan2_kernel() {
    int acc = 0;
    for (int b = 0; b < SCAN_NB; ++b) {
        int t = g_bsum[b];
        g_bsum[b] = acc;
        acc += t;
    }
}

// ---------------- 2c: final exclusive scan -> g_off, g_pos ----------------
__global__ void scan3_kernel() {
    __shared__ int sh[SCAN_T];
    const int tid = threadIdx.x;
    const int base = blockIdx.x * SCAN_BLK + tid * SCAN_C;
    int loc[SCAN_C];
    int s = 0;
    #pragma unroll
    for (int k = 0; k < SCAN_C; ++k) {
        int i = base + k;
        int c = (i < N_NODE) ? g_cnt[i] : 0;
        loc[k] = s;
        s += c;
    }
    sh[tid] = s;
    __syncthreads();
    // Hillis-Steele inclusive scan over per-thread sums
    for (int o = 1; o < SCAN_T; o <<= 1) {
        int v = (tid >= o) ? sh[tid - o] : 0;
        __syncthreads();
        sh[tid] += v;
        __syncthreads();
    }
    const int toff = g_bsum[blockIdx.x] + sh[tid] - s;  // exclusive thread offset
    #pragma unroll
    for (int k = 0; k < SCAN_C; ++k) {
        int i = base + k;
        if (i < N_NODE) {
            int o = toff + loc[k];
            g_off[i] = o;
            g_pos[i] = o;
        }
    }
    if (blockIdx.x == 0 && tid == 0) g_off[N_NODE] = NNZ;
}

// ---------------- 3: scatter edges into row-sorted order ----------------
__global__ void scatter_kernel(const int* __restrict__ rows,
                               const int* __restrict__ cols,
                               const float* __restrict__ vals) {
    int e = blockIdx.x * blockDim.x + threadIdx.x;
    if (e >= NNZ) return;
    int r = rows[e];
    int p = atomicAdd(&g_pos[r], 1);
    g_cv[p] = make_int2(cols[e], __float_as_int(vals[e]));
}

// ---------------- 4: CSR SpMM, warp per row, register accumulation ----------------
// Layer 1 reads layer-0 embeddings directly from emb_u/emb_i (virtual concat),
// saving the init/copy pass entirely.

__device__ __forceinline__ float2 ld_emb(const float2* __restrict__ eu,
                                         const float2* __restrict__ ei,
                                         int c, int lane) {
    return (c < N_USER) ? eu[(size_t)c * D2 + lane]
                        : ei[(size_t)(c - N_USER) * D2 + lane];
}

__global__ void __launch_bounds__(256)
spmm_csr_first_kernel(const float2* __restrict__ eu,
                      const float2* __restrict__ ei,
                      float2* __restrict__ y) {
    const int w = (blockIdx.x * blockDim.x + threadIdx.x) >> 5;
    const int lane = threadIdx.x & 31;
    if (w >= N_NODE) return;

    const int beg = g_off[w];
    const int end = g_off[w + 1];
    float2 acc = make_float2(0.f, 0.f);

    int e = beg;
    for (; e + 4 <= end; e += 4) {
        int2 cv0 = g_cv[e], cv1 = g_cv[e + 1], cv2 = g_cv[e + 2], cv3 = g_cv[e + 3];
        float2 a0 = ld_emb(eu, ei, cv0.x, lane);
        float2 a1 = ld_emb(eu, ei, cv1.x, lane);
        float2 a2 = ld_emb(eu, ei, cv2.x, lane);
        float2 a3 = ld_emb(eu, ei, cv3.x, lane);
        float v0 = __int_as_float(cv0.y), v1 = __int_as_float(cv1.y);
        float v2 = __int_as_float(cv2.y), v3 = __int_as_float(cv3.y);
        acc.x = fmaf(v0, a0.x, acc.x); acc.y = fmaf(v0, a0.y, acc.y);
        acc.x = fmaf(v1, a1.x, acc.x); acc.y = fmaf(v1, a1.y, acc.y);
        acc.x = fmaf(v2, a2.x, acc.x); acc.y = fmaf(v2, a2.y, acc.y);
        acc.x = fmaf(v3, a3.x, acc.x); acc.y = fmaf(v3, a3.y, acc.y);
    }
    for (; e < end; ++e) {
        int2 cv = g_cv[e];
        float2 a = ld_emb(eu, ei, cv.x, lane);
        float v = __int_as_float(cv.y);
        acc.x = fmaf(v, a.x, acc.x);
        acc.y = fmaf(v, a.y, acc.y);
    }
    y[(size_t)w * D2 + lane] = acc;
}

__global__ void __launch_bounds__(256)
spmm_csr_kernel(const float2* __restrict__ xin,
                float2* __restrict__ y) {
    const int w = (blockIdx.x * blockDim.x + threadIdx.x) >> 5;
    const int lane = threadIdx.x & 31;
    if (w >= N_NODE) return;

    const int beg = g_off[w];
    const int end = g_off[w + 1];
    float2 acc = make_float2(0.f, 0.f);

    int e = beg;
    for (; e + 4 <= end; e += 4) {
        int2 cv0 = g_cv[e], cv1 = g_cv[e + 1], cv2 = g_cv[e + 2], cv3 = g_cv[e + 3];
        float2 a0 = xin[(size_t)cv0.x * D2 + lane];
        float2 a1 = xin[(size_t)cv1.x * D2 + lane];
        float2 a2 = xin[(size_t)cv2.x * D2 + lane];
        float2 a3 = xin[(size_t)cv3.x * D2 + lane];
        float v0 = __int_as_float(cv0.y), v1 = __int_as_float(cv1.y);
        float v2 = __int_as_float(cv2.y), v3 = __int_as_float(cv3.y);
        acc.x = fmaf(v0, a0.x, acc.x); acc.y = fmaf(v0, a0.y, acc.y);
        acc.x = fmaf(v1, a1.x, acc.x); acc.y = fmaf(v1, a1.y, acc.y);
        acc.x = fmaf(v2, a2.x, acc.x); acc.y = fmaf(v2, a2.y, acc.y);
        acc.x = fmaf(v3, a3.x, acc.x); acc.y = fmaf(v3, a3.y, acc.y);
    }
    for (; e < end; ++e) {
        int2 cv = g_cv[e];
        float2 a = xin[(size_t)cv.x * D2 + lane];
        float v = __int_as_float(cv.y);
        acc.x = fmaf(v, a.x, acc.x);
        acc.y = fmaf(v, a.y, acc.y);
    }
    y[(size_t)w * D2 + lane] = acc;
}

// ---------------- 5: final gather + layer-sum + dot ----------------
// out[b] = (1/16) * sum_d (sum_l xl[u][d]) * (sum_l xl[i][d]); x0 read from emb.
__global__ void dot_kernel(const float* __restrict__ eu,
                           const float* __restrict__ ei,
                           const int* __restrict__ idx_u,
                           const int* __restrict__ idx_i,
                           float* __restrict__ out) {
    const int w = (blockIdx.x * blockDim.x + threadIdx.x) >> 5;
    const int lane = threadIdx.x & 31;
    if (w >= BATCH) return;

    const int un = idx_u[w];
    const int in = idx_i[w];
    const size_t u_node = (size_t)un * D;
    const size_t i_node = ((size_t)N_USER + in) * D;

    float partial = 0.f;
    #pragma unroll
    for (int k = 0; k < 2; ++k) {
        const int d = lane + k * 32;
        float u = eu[(size_t)un * D + d]
                + g_x1[u_node + d] + g_x2[u_node + d] + g_x3[u_node + d];
        float it = ei[(size_t)in * D + d]
                 + g_x1[i_node + d] + g_x2[i_node + d] + g_x3[i_node + d];
        partial = fmaf(u, it, partial);
    }
    #pragma unroll
    for (int off = 16; off > 0; off >>= 1)
        partial += __shfl_down_sync(0xFFFFFFFFu, partial, off);

    if (lane == 0)
        out[w] = partial * (1.0f / 16.0f);
}

// ---------------- launcher ----------------
extern "C" void kernel_launch(void* const* d_in, const int* in_sizes, int n_in,
                              void* d_out, int out_size) {
    const float* emb_u    = (const float*)d_in[0];
    const float* emb_i    = (const float*)d_in[1];
    const int*   adj_rows = (const int*)d_in[2];
    const int*   adj_cols = (const int*)d_in[3];
    const float* adj_vals = (const float*)d_in[4];
    const int*   idx_u    = (const int*)d_in[5];
    const int*   idx_i    = (const int*)d_in[6];
    float* out = (float*)d_out;

    float* x1; float* x2; float* x3;
    cudaGetSymbolAddress((void**)&x1, g_x1);
    cudaGetSymbolAddress((void**)&x2, g_x2);
    cudaGetSymbolAddress((void**)&x3, g_x3);

    // counting-sort pipeline: build row-sorted CSR edges
    zero_cnt_kernel<<<(N_NODE + 255) / 256, 256>>>();
    hist_kernel<<<(NNZ + 255) / 256, 256>>>(adj_rows);
    scan1_kernel<<<SCAN_NB, SCAN_T>>>();
    scan2_kernel<<<1, 1>>>();
    scan3_kernel<<<SCAN_NB, SCAN_T>>>();
    scatter_kernel<<<(NNZ + 511) / 512, 512>>>(adj_rows, adj_cols, adj_vals);

    // 3 SpMM layers, warp per row (no atomics, no zero-init needed)
    {
        const int threads = 256;                          // 8 warps/block
        const int blocks = (N_NODE + 7) / 8;              // 37500
        spmm_csr_first_kernel<<<blocks, threads>>>(
            (const float2*)emb_u, (const float2*)emb_i, (float2*)x1);
        spmm_csr_kernel<<<blocks, threads>>>((const float2*)x1, (float2*)x2);
        spmm_csr_kernel<<<blocks, threads>>>((const float2*)x2, (float2*)x3);
    }

    // final gather + dot: one warp per pair
    {
        const int threads = 256;
        const int blocks = (BATCH * 32 + threads - 1) / threads;
        dot_kernel<<<blocks, threads>>>(emb_u, emb_i, idx_u, idx_i, out);
    }
}

// round 6
// speedup vs baseline: 2.3190x; 1.5069x over previous
#include <cuda_runtime.h>
#include <cuda_bf16.h>
#include <cstdint>

// ---------------- problem constants ----------------
#define N_USER 200000
#define N_ITEM 100000
#define N_NODE 300000
#define D 64
#define NNZ 2000000
#define BATCH 8192

#define D2 (D / 2)   // float2 per row = 32

// ---------------- scan config ----------------
#define SCAN_T 256
#define SCAN_C 8
#define SCAN_BLK (SCAN_T * SCAN_C)                      // 2048
#define SCAN_NB ((N_NODE + SCAN_BLK - 1) / SCAN_BLK)    // 147

// ---------------- scratch (device globals) ----------------
__device__ float g_x1[(size_t)N_NODE * D];
__device__ float g_x2[(size_t)N_NODE * D];
__device__ int   g_cnt[N_NODE];
__device__ int   g_need[N_NODE];     // rows where layer-2 output is required
__device__ int   g_off[N_NODE + 1];
__device__ int   g_pos[N_NODE];
__device__ int   g_bsum[SCAN_NB];
__device__ int2  g_cv[NNZ];          // packed (col, bitcast(val)) sorted by row

// ---------------- 0: zero counts + need flags ----------------
__global__ void zero_kernel() {
    int i = blockIdx.x * blockDim.x + threadIdx.x;
    if (i < N_NODE) { g_cnt[i] = 0; g_need[i] = 0; }
}

// ---------------- 1: histogram of row degrees ----------------
__global__ void hist_kernel(const int* __restrict__ rows) {
    int e = blockIdx.x * blockDim.x + threadIdx.x;
    if (e < NNZ) atomicAdd(&g_cnt[rows[e]], 1);
}

// ---------------- 2a: per-block sums ----------------
__global__ void scan1_kernel() {
    __shared__ int sh[SCAN_T];
    const int tid = threadIdx.x;
    const int base = blockIdx.x * SCAN_BLK + tid * SCAN_C;
    int s = 0;
    #pragma unroll
    for (int k = 0; k < SCAN_C; ++k) {
        int i = base + k;
        s += (i < N_NODE) ? g_cnt[i] : 0;
    }
    sh[tid] = s;
    __syncthreads();
    for (int o = SCAN_T / 2; o > 0; o >>= 1) {
        if (tid < o) sh[tid] += sh[tid + o];
        __syncthreads();
    }
    if (tid == 0) g_bsum[blockIdx.x] = sh[0];
}

// ---------------- 2b: one-block parallel exclusive scan of block sums ----------------
__global__ void scan2_kernel() {
    __shared__ int sh[256];
    const int tid = threadIdx.x;
    int v = (tid < SCAN_NB) ? g_bsum[tid] : 0;
    sh[tid] = v;
    __syncthreads();
    for (int o = 1; o < 256; o <<= 1) {
        int t = (tid >= o) ? sh[tid - o] : 0;
        __syncthreads();
        sh[tid] += t;
        __syncthreads();
    }
    if (tid < SCAN_NB) g_bsum[tid] = sh[tid] - v;   // exclusive
}

// ---------------- 2c: final exclusive scan -> g_off, g_pos ----------------
__global__ void scan3_kernel() {
    __shared__ int sh[SCAN_T];
    const int tid = threadIdx.x;
    const int base = blockIdx.x * SCAN_BLK + tid * SCAN_C;
    int loc[SCAN_C];
    int s = 0;
    #pragma unroll
    for (int k = 0; k < SCAN_C; ++k) {
        int i = base + k;
        int c = (i < N_NODE) ? g_cnt[i] : 0;
        loc[k] = s;
        s += c;
    }
    sh[tid] = s;
    __syncthreads();
    for (int o = 1; o < SCAN_T; o <<= 1) {
        int v = (tid >= o) ? sh[tid - o] : 0;
        __syncthreads();
        sh[tid] += v;
        __syncthreads();
    }
    const int toff = g_bsum[blockIdx.x] + sh[tid] - s;
    #pragma unroll
    for (int k = 0; k < SCAN_C; ++k) {
        int i = base + k;
        if (i < N_NODE) {
            int o = toff + loc[k];
            g_off[i] = o;
            g_pos[i] = o;
        }
    }
    if (blockIdx.x == 0 && tid == 0) g_off[N_NODE] = NNZ;
}

// ---------------- 3: scatter edges into row-sorted order ----------------
__global__ void scatter_kernel(const int* __restrict__ rows,
                               const int* __restrict__ cols,
                               const float* __restrict__ vals) {
    int e = blockIdx.x * blockDim.x + threadIdx.x;
    if (e >= NNZ) return;
    int r = rows[e];
    int p = atomicAdd(&g_pos[r], 1);
    g_cv[p] = make_int2(cols[e], __float_as_int(vals[e]));
}

// ---------------- 3b: mark rows where layer-2 output is needed ----------------
// need2 = S (gathered nodes) ∪ N(S) (their edge cols); x3 is computed on the
// fly in the dot kernel from x2 at exactly these rows.
__global__ void mark_kernel(const int* __restrict__ idx_u,
                            const int* __restrict__ idx_i) {
    int t = blockIdx.x * blockDim.x + threadIdx.x;
    if (t >= 2 * BATCH) return;
    int node = (t < BATCH) ? idx_u[t] : (N_USER + idx_i[t - BATCH]);
    g_need[node] = 1;
    const int end = g_off[node + 1];
    for (int e = g_off[node]; e < end; ++e)
        g_need[g_cv[e].x] = 1;
}

// ---------------- 4: CSR SpMM, warp per row, register accumulation ----------------
__device__ __forceinline__ float2 ld_emb(const float2* __restrict__ eu,
                                         const float2* __restrict__ ei,
                                         int c, int lane) {
    return (c < N_USER) ? eu[(size_t)c * D2 + lane]
                        : ei[(size_t)(c - N_USER) * D2 + lane];
}

__global__ void __launch_bounds__(256)
spmm_csr_first_kernel(const float2* __restrict__ eu,
                      const float2* __restrict__ ei,
                      float2* __restrict__ y) {
    const int w = (blockIdx.x * blockDim.x + threadIdx.x) >> 5;
    const int lane = threadIdx.x & 31;
    if (w >= N_NODE) return;

    const int beg = g_off[w];
    const int end = g_off[w + 1];
    float2 acc = make_float2(0.f, 0.f);

    int e = beg;
    for (; e + 4 <= end; e += 4) {
        int2 cv0 = g_cv[e], cv1 = g_cv[e + 1], cv2 = g_cv[e + 2], cv3 = g_cv[e + 3];
        float2 a0 = ld_emb(eu, ei, cv0.x, lane);
        float2 a1 = ld_emb(eu, ei, cv1.x, lane);
        float2 a2 = ld_emb(eu, ei, cv2.x, lane);
        float2 a3 = ld_emb(eu, ei, cv3.x, lane);
        float v0 = __int_as_float(cv0.y), v1 = __int_as_float(cv1.y);
        float v2 = __int_as_float(cv2.y), v3 = __int_as_float(cv3.y);
        acc.x = fmaf(v0, a0.x, acc.x); acc.y = fmaf(v0, a0.y, acc.y);
        acc.x = fmaf(v1, a1.x, acc.x); acc.y = fmaf(v1, a1.y, acc.y);
        acc.x = fmaf(v2, a2.x, acc.x); acc.y = fmaf(v2, a2.y, acc.y);
        acc.x = fmaf(v3, a3.x, acc.x); acc.y = fmaf(v3, a3.y, acc.y);
    }
    for (; e < end; ++e) {
        int2 cv = g_cv[e];
        float2 a = ld_emb(eu, ei, cv.x, lane);
        float v = __int_as_float(cv.y);
        acc.x = fmaf(v, a.x, acc.x);
        acc.y = fmaf(v, a.y, acc.y);
    }
    y[(size_t)w * D2 + lane] = acc;
}

// Layer 2: only compute rows flagged in g_need (≈40% of nodes).
__global__ void __launch_bounds__(256)
spmm_csr_flag_kernel(const float2* __restrict__ xin,
                     float2* __restrict__ y) {
    const int w = (blockIdx.x * blockDim.x + threadIdx.x) >> 5;
    const int lane = threadIdx.x & 31;
    if (w >= N_NODE) return;
    if (!g_need[w]) return;          // broadcast load, early exit

    const int beg = g_off[w];
    const int end = g_off[w + 1];
    float2 acc = make_float2(0.f, 0.f);

    int e = beg;
    for (; e + 4 <= end; e += 4) {
        int2 cv0 = g_cv[e], cv1 = g_cv[e + 1], cv2 = g_cv[e + 2], cv3 = g_cv[e + 3];
        float2 a0 = xin[(size_t)cv0.x * D2 + lane];
        float2 a1 = xin[(size_t)cv1.x * D2 + lane];
        float2 a2 = xin[(size_t)cv2.x * D2 + lane];
        float2 a3 = xin[(size_t)cv3.x * D2 + lane];
        float v0 = __int_as_float(cv0.y), v1 = __int_as_float(cv1.y);
        float v2 = __int_as_float(cv2.y), v3 = __int_as_float(cv3.y);
        acc.x = fmaf(v0, a0.x, acc.x); acc.y = fmaf(v0, a0.y, acc.y);
        acc.x = fmaf(v1, a1.x, acc.x); acc.y = fmaf(v1, a1.y, acc.y);
        acc.x = fmaf(v2, a2.x, acc.x); acc.y = fmaf(v2, a2.y, acc.y);
        acc.x = fmaf(v3, a3.x, acc.x); acc.y = fmaf(v3, a3.y, acc.y);
    }
    for (; e < end; ++e) {
        int2 cv = g_cv[e];
        float2 a = xin[(size_t)cv.x * D2 + lane];
        float v = __int_as_float(cv.y);
        acc.x = fmaf(v, a.x, acc.x);
        acc.y = fmaf(v, a.y, acc.y);
    }
    y[(size_t)w * D2 + lane] = acc;
}

// ---------------- 5: dot with fused layer-3 ----------------
// s[node] = e0 + x1 + x2 + x3, where x3 = Σ_e val · x2[col] computed on the fly.
__device__ __forceinline__ float2 node_sum(const float* __restrict__ emb,
                                           size_t erow, int node, int lane) {
    const size_t nb = (size_t)node * D;
    float2 s;
    s.x = emb[erow * D + lane]      + g_x1[nb + lane]      + g_x2[nb + lane];
    s.y = emb[erow * D + lane + 32] + g_x1[nb + lane + 32] + g_x2[nb + lane + 32];

    const int beg = g_off[node];
    const int end = g_off[node + 1];
    int e = beg;
    float2 t0 = make_float2(0.f, 0.f), t1 = make_float2(0.f, 0.f);
    for (; e + 2 <= end; e += 2) {
        int2 cv0 = g_cv[e], cv1 = g_cv[e + 1];
        const size_t c0 = (size_t)cv0.x * D, c1 = (size_t)cv1.x * D;
        float v0 = __int_as_float(cv0.y), v1 = __int_as_float(cv1.y);
        t0.x = fmaf(v0, g_x2[c0 + lane],      t0.x);
        t0.y = fmaf(v0, g_x2[c0 + lane + 32], t0.y);
        t1.x = fmaf(v1, g_x2[c1 + lane],      t1.x);
        t1.y = fmaf(v1, g_x2[c1 + lane + 32], t1.y);
    }
    if (e < end) {
        int2 cv = g_cv[e];
        const size_t c = (size_t)cv.x * D;
        float v = __int_as_float(cv.y);
        t0.x = fmaf(v, g_x2[c + lane],      t0.x);
        t0.y = fmaf(v, g_x2[c + lane + 32], t0.y);
    }
    s.x += t0.x + t1.x;
    s.y += t0.y + t1.y;
    return s;
}

__global__ void dot_kernel(const float* __restrict__ eu,
                           const float* __restrict__ ei,
                           const int* __restrict__ idx_u,
                           const int* __restrict__ idx_i,
                           float* __restrict__ out) {
    const int w = (blockIdx.x * blockDim.x + threadIdx.x) >> 5;
    const int lane = threadIdx.x & 31;
    if (w >= BATCH) return;

    const int un = idx_u[w];
    const int in = idx_i[w];

    float2 su = node_sum(eu, (size_t)un, un, lane);
    float2 si = node_sum(ei, (size_t)in, N_USER + in, lane);

    float partial = su.x * si.x + su.y * si.y;
    #pragma unroll
    for (int off = 16; off > 0; off >>= 1)
        partial += __shfl_down_sync(0xFFFFFFFFu, partial, off);

    if (lane == 0)
        out[w] = partial * (1.0f / 16.0f);
}

// ---------------- launcher ----------------
extern "C" void kernel_launch(void* const* d_in, const int* in_sizes, int n_in,
                              void* d_out, int out_size) {
    const float* emb_u    = (const float*)d_in[0];
    const float* emb_i    = (const float*)d_in[1];
    const int*   adj_rows = (const int*)d_in[2];
    const int*   adj_cols = (const int*)d_in[3];
    const float* adj_vals = (const float*)d_in[4];
    const int*   idx_u    = (const int*)d_in[5];
    const int*   idx_i    = (const int*)d_in[6];
    float* out = (float*)d_out;

    float* x1; float* x2;
    cudaGetSymbolAddress((void**)&x1, g_x1);
    cudaGetSymbolAddress((void**)&x2, g_x2);

    // counting-sort pipeline: build row-sorted CSR edges
    zero_kernel<<<(N_NODE + 255) / 256, 256>>>();
    hist_kernel<<<(NNZ + 255) / 256, 256>>>(adj_rows);
    scan1_kernel<<<SCAN_NB, SCAN_T>>>();
    scan2_kernel<<<1, 256>>>();
    scan3_kernel<<<SCAN_NB, SCAN_T>>>();
    scatter_kernel<<<(NNZ + 511) / 512, 512>>>(adj_rows, adj_cols, adj_vals);

    // mark rows where layer-2 output is required (S ∪ N(S))
    mark_kernel<<<(2 * BATCH + 255) / 256, 256>>>(idx_u, idx_i);

    // layer 1 (full), layer 2 (sparsified); layer 3 fused into dot
    {
        const int threads = 256;                          // 8 warps/block
        const int blocks = (N_NODE + 7) / 8;              // 37500
        spmm_csr_first_kernel<<<blocks, threads>>>(
            (const float2*)emb_u, (const float2*)emb_i, (float2*)x1);
        spmm_csr_flag_kernel<<<blocks, threads>>>((const float2*)x1, (float2*)x2);
    }

    // dot with fused layer-3: one warp per pair
    {
        const int threads = 256;
        const int blocks = (BATCH * 32 + threads - 1) / threads;
        dot_kernel<<<blocks, threads>>>(emb_u, emb_i, idx_u, idx_i, out);
    }
}

// round 9
// speedup vs baseline: 2.3391x; 1.0087x over previous
#include <cuda_runtime.h>
#include <cuda_bf16.h>
#include <cstdint>

// ---------------- problem constants ----------------
#define N_USER 200000
#define N_ITEM 100000
#define N_NODE 300000
#define D 64
#define NNZ 2000000
#define BATCH 8192

#define D2 (D / 2)   // float2 per row = 32

// ---------------- scan config ----------------
#define SCAN_T 256
#define SCAN_C 8
#define SCAN_BLK (SCAN_T * SCAN_C)                      // 2048
#define SCAN_NB ((N_NODE + SCAN_BLK - 1) / SCAN_BLK)    // 147

// ---------------- scratch (device globals) ----------------
__device__ float g_x1[(size_t)N_NODE * D];
__device__ float g_x2[(size_t)N_NODE * D];
__device__ __align__(16) int g_cnt[N_NODE];
__device__ __align__(16) int g_need[N_NODE];   // rows where layer-2 output is required
__device__ int   g_off[N_NODE + 1];
__device__ int   g_pos[N_NODE];
__device__ int   g_bsum[SCAN_NB];
__device__ int2  g_cv[NNZ];          // packed (col, bitcast(val)) sorted by row

// ---------------- 0: zero counts + need flags (vectorized) ----------------
__global__ void zero_kernel() {
    const int n4 = N_NODE / 4;   // 75000, N_NODE divisible by 4
    int i = blockIdx.x * blockDim.x + threadIdx.x;
    if (i < n4) {
        const int4 z = make_int4(0, 0, 0, 0);
        reinterpret_cast<int4*>(g_cnt)[i] = z;
        reinterpret_cast<int4*>(g_need)[i] = z;
    }
}

// ---------------- 1: histogram of row degrees ----------------
__global__ void hist_kernel(const int* __restrict__ rows) {
    int e = blockIdx.x * blockDim.x + threadIdx.x;
    if (e < NNZ) atomicAdd(&g_cnt[rows[e]], 1);
}

// ---------------- 2a: per-block sums ----------------
__global__ void scan1_kernel() {
    __shared__ int sh[SCAN_T];
    const int tid = threadIdx.x;
    const int base = blockIdx.x * SCAN_BLK + tid * SCAN_C;
    int s = 0;
    #pragma unroll
    for (int k = 0; k < SCAN_C; ++k) {
        int i = base + k;
        s += (i < N_NODE) ? g_cnt[i] : 0;
    }
    sh[tid] = s;
    __syncthreads();
    for (int o = SCAN_T / 2; o > 0; o >>= 1) {
        if (tid < o) sh[tid] += sh[tid + o];
        __syncthreads();
    }
    if (tid == 0) g_bsum[blockIdx.x] = sh[0];
}

// ---------------- 2b: final exclusive scan -> g_off, g_pos ----------------
// Each block redundantly scans the 147-entry g_bsum array in shared memory
// (replaces the former separate scan2 launch).
__global__ void scan3_kernel() {
    __shared__ int sb[256];
    __shared__ int sh[SCAN_T];
    const int tid = threadIdx.x;

    // parallel inclusive scan of block sums (padded to 256)
    int bv = (tid < SCAN_NB) ? g_bsum[tid] : 0;
    sb[tid] = bv;
    __syncthreads();
    for (int o = 1; o < 256; o <<= 1) {
        int t = (tid >= o) ? sb[tid - o] : 0;
        __syncthreads();
        sb[tid] += t;
        __syncthreads();
    }
    const int block_base = (blockIdx.x > 0) ? sb[blockIdx.x - 1] : 0;

    const int base = blockIdx.x * SCAN_BLK + tid * SCAN_C;
    int loc[SCAN_C];
    int s = 0;
    #pragma unroll
    for (int k = 0; k < SCAN_C; ++k) {
        int i = base + k;
        int c = (i < N_NODE) ? g_cnt[i] : 0;
        loc[k] = s;
        s += c;
    }
    sh[tid] = s;
    __syncthreads();
    for (int o = 1; o < SCAN_T; o <<= 1) {
        int v = (tid >= o) ? sh[tid - o] : 0;
        __syncthreads();
        sh[tid] += v;
        __syncthreads();
    }
    const int toff = block_base + sh[tid] - s;   // exclusive thread offset
    #pragma unroll
    for (int k = 0; k < SCAN_C; ++k) {
        int i = base + k;
        if (i < N_NODE) {
            int o = toff + loc[k];
            g_off[i] = o;
            g_pos[i] = o;
        }
    }
    if (blockIdx.x == 0 && tid == 0) g_off[N_NODE] = NNZ;
}

// ---------------- 3: scatter edges into row-sorted order ----------------
__global__ void scatter_kernel(const int* __restrict__ rows,
                               const int* __restrict__ cols,
                               const float* __restrict__ vals) {
    int e = blockIdx.x * blockDim.x + threadIdx.x;
    if (e >= NNZ) return;
    int r = rows[e];
    int p = atomicAdd(&g_pos[r], 1);
    g_cv[p] = make_int2(cols[e], __float_as_int(vals[e]));
}

// ---------------- 3b: mark rows where layer-2 output is needed ----------------
// need2 = S (gathered nodes) ∪ N(S) (their edge cols); x3 is computed on the
// fly in the dot kernel from x2 at exactly these rows.
__global__ void mark_kernel(const int* __restrict__ idx_u,
                            const int* __restrict__ idx_i) {
    int t = blockIdx.x * blockDim.x + threadIdx.x;
    if (t >= 2 * BATCH) return;
    int node = (t < BATCH) ? idx_u[t] : (N_USER + idx_i[t - BATCH]);
    g_need[node] = 1;
    const int end = g_off[node + 1];
    for (int e = g_off[node]; e < end; ++e)
        g_need[g_cv[e].x] = 1;
}

// ---------------- 4: CSR SpMM, warp per row, register accumulation ----------------
__device__ __forceinline__ float2 ld_emb(const float2* __restrict__ eu,
                                         const float2* __restrict__ ei,
                                         int c, int lane) {
    return (c < N_USER) ? eu[(size_t)c * D2 + lane]
                        : ei[(size_t)(c - N_USER) * D2 + lane];
}

__global__ void __launch_bounds__(256)
spmm_csr_first_kernel(const float2* __restrict__ eu,
                      const float2* __restrict__ ei,
                      float2* __restrict__ y) {
    const int w = (blockIdx.x * blockDim.x + threadIdx.x) >> 5;
    const int lane = threadIdx.x & 31;
    if (w >= N_NODE) return;

    const int beg = g_off[w];
    const int end = g_off[w + 1];
    float2 acc = make_float2(0.f, 0.f);

    int e = beg;
    for (; e + 4 <= end; e += 4) {
        int2 cv0 = g_cv[e], cv1 = g_cv[e + 1], cv2 = g_cv[e + 2], cv3 = g_cv[e + 3];
        float2 a0 = ld_emb(eu, ei, cv0.x, lane);
        float2 a1 = ld_emb(eu, ei, cv1.x, lane);
        float2 a2 = ld_emb(eu, ei, cv2.x, lane);
        float2 a3 = ld_emb(eu, ei, cv3.x, lane);
        float v0 = __int_as_float(cv0.y), v1 = __int_as_float(cv1.y);
        float v2 = __int_as_float(cv2.y), v3 = __int_as_float(cv3.y);
        acc.x = fmaf(v0, a0.x, acc.x); acc.y = fmaf(v0, a0.y, acc.y);
        acc.x = fmaf(v1, a1.x, acc.x); acc.y = fmaf(v1, a1.y, acc.y);
        acc.x = fmaf(v2, a2.x, acc.x); acc.y = fmaf(v2, a2.y, acc.y);
        acc.x = fmaf(v3, a3.x, acc.x); acc.y = fmaf(v3, a3.y, acc.y);
    }
    for (; e < end; ++e) {
        int2 cv = g_cv[e];
        float2 a = ld_emb(eu, ei, cv.x, lane);
        float v = __int_as_float(cv.y);
        acc.x = fmaf(v, a.x, acc.x);
        acc.y = fmaf(v, a.y, acc.y);
    }
    // evict-first store: keep the gather source (emb) resident in L2 instead
    // of letting 77 MB of streaming writes thrash it.
    __stcs(&y[(size_t)w * D2 + lane], acc);
}

// Layer 2: only compute rows flagged in g_need (≈40% of nodes).
__global__ void __launch_bounds__(256)
spmm_csr_flag_kernel(const float2* __restrict__ xin,
                     float2* __restrict__ y) {
    const int w = (blockIdx.x * blockDim.x + threadIdx.x) >> 5;
    const int lane = threadIdx.x & 31;
    if (w >= N_NODE) return;
    if (!g_need[w]) return;          // broadcast load, early exit

    const int beg = g_off[w];
    const int end = g_off[w + 1];
    float2 acc = make_float2(0.f, 0.f);

    int e = beg;
    for (; e + 4 <= end; e += 4) {
        int2 cv0 = g_cv[e], cv1 = g_cv[e + 1], cv2 = g_cv[e + 2], cv3 = g_cv[e + 3];
        float2 a0 = xin[(size_t)cv0.x * D2 + lane];
        float2 a1 = xin[(size_t)cv1.x * D2 + lane];
        float2 a2 = xin[(size_t)cv2.x * D2 + lane];
        float2 a3 = xin[(size_t)cv3.x * D2 + lane];
        float v0 = __int_as_float(cv0.y), v1 = __int_as_float(cv1.y);
        float v2 = __int_as_float(cv2.y), v3 = __int_as_float(cv3.y);
        acc.x = fmaf(v0, a0.x, acc.x); acc.y = fmaf(v0, a0.y, acc.y);
        acc.x = fmaf(v1, a1.x, acc.x); acc.y = fmaf(v1, a1.y, acc.y);
        acc.x = fmaf(v2, a2.x, acc.x); acc.y = fmaf(v2, a2.y, acc.y);
        acc.x = fmaf(v3, a3.x, acc.x); acc.y = fmaf(v3, a3.y, acc.y);
    }
    for (; e < end; ++e) {
        int2 cv = g_cv[e];
        float2 a = xin[(size_t)cv.x * D2 + lane];
        float v = __int_as_float(cv.y);
        acc.x = fmaf(v, a.x, acc.x);
        acc.y = fmaf(v, a.y, acc.y);
    }
    y[(size_t)w * D2 + lane] = acc;
}

// ---------------- 5: dot with fused layer-3 ----------------
// s[node] = e0 + x1 + x2 + x3, where x3 = Σ_e val · x2[col] computed on the fly.
__device__ __forceinline__ float2 node_sum(const float* __restrict__ emb,
                                           size_t erow, int node, int lane) {
    const size_t nb = (size_t)node * D;
    float2 s;
    s.x = emb[erow * D + lane]      + g_x1[nb + lane]      + g_x2[nb + lane];
    s.y = emb[erow * D + lane + 32] + g_x1[nb + lane + 32] + g_x2[nb + lane + 32];

    const int beg = g_off[node];
    const int end = g_off[node + 1];
    int e = beg;
    float2 t0 = make_float2(0.f, 0.f), t1 = make_float2(0.f, 0.f);
    for (; e + 2 <= end; e += 2) {
        int2 cv0 = g_cv[e], cv1 = g_cv[e + 1];
        const size_t c0 = (size_t)cv0.x * D, c1 = (size_t)cv1.x * D;
        float v0 = __int_as_float(cv0.y), v1 = __int_as_float(cv1.y);
        t0.x = fmaf(v0, g_x2[c0 + lane],      t0.x);
        t0.y = fmaf(v0, g_x2[c0 + lane + 32], t0.y);
        t1.x = fmaf(v1, g_x2[c1 + lane],      t1.x);
        t1.y = fmaf(v1, g_x2[c1 + lane + 32], t1.y);
    }
    if (e < end) {
        int2 cv = g_cv[e];
        const size_t c = (size_t)cv.x * D;
        float v = __int_as_float(cv.y);
        t0.x = fmaf(v, g_x2[c + lane],      t0.x);
        t0.y = fmaf(v, g_x2[c + lane + 32], t0.y);
    }
    s.x += t0.x + t1.x;
    s.y += t0.y + t1.y;
    return s;
}

__global__ void dot_kernel(const float* __restrict__ eu,
                           const float* __restrict__ ei,
                           const int* __restrict__ idx_u,
                           const int* __restrict__ idx_i,
                           float* __restrict__ out) {
    const int w = (blockIdx.x * blockDim.x + threadIdx.x) >> 5;
    const int lane = threadIdx.x & 31;
    if (w >= BATCH) return;

    const int un = idx_u[w];
    const int in = idx_i[w];

    float2 su = node_sum(eu, (size_t)un, un, lane);
    float2 si = node_sum(ei, (size_t)in, N_USER + in, lane);

    float partial = su.x * si.x + su.y * si.y;
    #pragma unroll
    for (int off = 16; off > 0; off >>= 1)
        partial += __shfl_down_sync(0xFFFFFFFFu, partial, off);

    if (lane == 0)
        out[w] = partial * (1.0f / 16.0f);
}

// ---------------- launcher ----------------
extern "C" void kernel_launch(void* const* d_in, const int* in_sizes, int n_in,
                              void* d_out, int out_size) {
    const float* emb_u    = (const float*)d_in[0];
    const float* emb_i    = (const float*)d_in[1];
    const int*   adj_rows = (const int*)d_in[2];
    const int*   adj_cols = (const int*)d_in[3];
    const float* adj_vals = (const float*)d_in[4];
    const int*   idx_u    = (const int*)d_in[5];
    const int*   idx_i    = (const int*)d_in[6];
    float* out = (float*)d_out;

    float* x1; float* x2;
    cudaGetSymbolAddress((void**)&x1, g_x1);
    cudaGetSymbolAddress((void**)&x2, g_x2);

    // counting-sort pipeline: build row-sorted CSR edges
    zero_kernel<<<(N_NODE / 4 + 255) / 256, 256>>>();
    hist_kernel<<<(NNZ + 255) / 256, 256>>>(adj_rows);
    scan1_kernel<<<SCAN_NB, SCAN_T>>>();
    scan3_kernel<<<SCAN_NB, SCAN_T>>>();
    scatter_kernel<<<(NNZ + 511) / 512, 512>>>(adj_rows, adj_cols, adj_vals);

    // mark rows where layer-2 output is required (S ∪ N(S))
    mark_kernel<<<(2 * BATCH + 255) / 256, 256>>>(idx_u, idx_i);

    // layer 1 (full), layer 2 (sparsified); layer 3 fused into dot
    {
        const int threads = 256;                          // 8 warps/block
        const int blocks = (N_NODE + 7) / 8;              // 37500
        spmm_csr_first_kernel<<<blocks, threads>>>(
            (const float2*)emb_u, (const float2*)emb_i, (float2*)x1);
        spmm_csr_flag_kernel<<<blocks, threads>>>((const float2*)x1, (float2*)x2);
    }

    // dot with fused layer-3: one warp per pair
    {
        const int threads = 256;
        const int blocks = (BATCH * 32 + threads - 1) / threads;
        dot_kernel<<<blocks, threads>>>(emb_u, emb_i, idx_u, idx_i, out);
    }
}